// round 14
// baseline (speedup 1.0000x reference)
#include <cuda_runtime.h>
#include <math_constants.h>

#define NN   512
#define DIN  128
#define HH   2
#define CC   200
#define HC   400
#define FCO  1000
#define ETOT_MAX (32768 + NN)

// ---------------- device-global scratch ---------------------------------------
__device__ float g_xl[NN * HC];
__device__ float g_xr[NN * HC];
__device__ float g_h [NN * HC];
__device__ int   g_rowptr[NN + 1];
__device__ int   g_col[ETOT_MAX];
__device__ float g_fc[FCO];
__device__ int   g_ticket;

// ---------------- CSR build: single block, 512 threads ------------------------
__global__ void csr_build_kernel(const int* __restrict__ ei, int E) {
    __shared__ int s[NN];
    __shared__ int cur[NN];
    int t = threadIdx.x;

    if (t < 500) { g_fc[t] = 0.f; g_fc[t + 500] = 0.f; }
    if (t == 0) g_ticket = 0;
    s[t] = 0;
    __syncthreads();

    int Etot = E + NN;
    for (int e = t; e < Etot; e += NN) {
        int dst = (e < E) ? ei[E + e] : (e - E);
        atomicAdd(&s[dst], 1);
    }
    __syncthreads();

    int cnt = s[t];
    #pragma unroll
    for (int off = 1; off < NN; off <<= 1) {
        int v = (t >= off) ? s[t - off] : 0;
        __syncthreads();
        s[t] += v;
        __syncthreads();
    }
    g_rowptr[t + 1] = s[t];
    if (t == 0) g_rowptr[0] = 0;
    cur[t] = s[t] - cnt;          // exclusive prefix
    __syncthreads();

    for (int e = t; e < Etot; e += NN) {
        int src, dst;
        if (e < E) { src = ei[e]; dst = ei[E + e]; }
        else       { src = dst = e - E; }
        int p = atomicAdd(&cur[dst], 1);
        g_col[p] = src;
    }
}

// ---------------- GEMM: 16x64 tile, BK=16, 128 threads, 2x4 microtile ----------
__global__ void __launch_bounds__(128)
gemm_kernel(const float* __restrict__ Aext, int useAext,
            const float* __restrict__ Wl, const float* __restrict__ bl,
            const float* __restrict__ Wr, const float* __restrict__ br,
            int K) {
    const float* A    = useAext ? Aext : g_h;
    const float* B    = blockIdx.z ? Wr : Wl;
    const float* bias = blockIdx.z ? br : bl;
    float*       Cout = blockIdx.z ? g_xr : g_xl;

    __shared__ float As[16][17];
    __shared__ float Bs[16][64];

    const int tid = threadIdx.x;
    const int tx = tid & 15;
    const int ty = tid >> 4;
    const int rowBase = blockIdx.y * 16;
    const int colBase = blockIdx.x * 64;

    const int a_m  = tid >> 3;
    const int a_k2 = (tid & 7) * 2;
    const int b_k  = tid >> 3;
    const int b_n8 = (tid & 7) * 8;

    const int nTiles = K >> 4;

    float2 pa;
    float4 pb0, pb1;

    {
        pa = *reinterpret_cast<const float2*>(&A[(rowBase + a_m) * K + a_k2]);
        int ncol = colBase + b_n8;
        if (ncol + 7 < HC) {
            pb0 = *reinterpret_cast<const float4*>(&B[b_k * HC + ncol]);
            pb1 = *reinterpret_cast<const float4*>(&B[b_k * HC + ncol + 4]);
        } else {
            float tmp[8];
            #pragma unroll
            for (int j = 0; j < 8; j++)
                tmp[j] = (ncol + j < HC) ? B[b_k * HC + ncol + j] : 0.f;
            pb0 = make_float4(tmp[0], tmp[1], tmp[2], tmp[3]);
            pb1 = make_float4(tmp[4], tmp[5], tmp[6], tmp[7]);
        }
    }

    float acc[2][4];
    #pragma unroll
    for (int i = 0; i < 2; i++)
        #pragma unroll
        for (int j = 0; j < 4; j++) acc[i][j] = 0.f;

    for (int t = 0; t < nTiles; t++) {
        As[a_k2 + 0][a_m] = pa.x;
        As[a_k2 + 1][a_m] = pa.y;
        *reinterpret_cast<float4*>(&Bs[b_k][b_n8])     = pb0;
        *reinterpret_cast<float4*>(&Bs[b_k][b_n8 + 4]) = pb1;
        __syncthreads();

        if (t + 1 < nTiles) {
            int k0 = (t + 1) << 4;
            pa = *reinterpret_cast<const float2*>(&A[(rowBase + a_m) * K + k0 + a_k2]);
            int ncol = colBase + b_n8;
            if (ncol + 7 < HC) {
                pb0 = *reinterpret_cast<const float4*>(&B[(k0 + b_k) * HC + ncol]);
                pb1 = *reinterpret_cast<const float4*>(&B[(k0 + b_k) * HC + ncol + 4]);
            } else {
                float tmp[8];
                #pragma unroll
                for (int j = 0; j < 8; j++)
                    tmp[j] = (ncol + j < HC) ? B[(k0 + b_k) * HC + ncol + j] : 0.f;
                pb0 = make_float4(tmp[0], tmp[1], tmp[2], tmp[3]);
                pb1 = make_float4(tmp[4], tmp[5], tmp[6], tmp[7]);
            }
        }

        #pragma unroll
        for (int k = 0; k < 16; k++) {
            float a0 = As[k][2 * ty];
            float a1 = As[k][2 * ty + 1];
            float4 b = *reinterpret_cast<const float4*>(&Bs[k][4 * tx]);
            acc[0][0] = fmaf(a0, b.x, acc[0][0]);
            acc[0][1] = fmaf(a0, b.y, acc[0][1]);
            acc[0][2] = fmaf(a0, b.z, acc[0][2]);
            acc[0][3] = fmaf(a0, b.w, acc[0][3]);
            acc[1][0] = fmaf(a1, b.x, acc[1][0]);
            acc[1][1] = fmaf(a1, b.y, acc[1][1]);
            acc[1][2] = fmaf(a1, b.z, acc[1][2]);
            acc[1][3] = fmaf(a1, b.w, acc[1][3]);
        }
        __syncthreads();
    }

    const int r0 = rowBase + 2 * ty;
    const int c0 = colBase + 4 * tx;
    #pragma unroll
    for (int j = 0; j < 4; j++) {
        int c = c0 + j;
        if (c < HC) {
            float bb = bias[c];
            Cout[r0 * HC + c]       = acc[0][j] + bb;
            Cout[(r0 + 1) * HC + c] = acc[1][j] + bb;
        }
    }
}

// ---------------- GATv2 attention (layers 0,1) ---------------------------------
__global__ void attn_kernel(const float* __restrict__ att,
                            const float* __restrict__ bias,
                            int do_relu) {
    const int n    = blockIdx.x >> 1;
    const int hh   = blockIdx.x & 1;
    const int warp = threadIdx.x >> 5;
    const int lane = threadIdx.x & 31;
    const int base = hh * CC;

    __shared__ float sm_m[4];
    __shared__ float sm_d[4];
    __shared__ float sm_acc[4][CC];

    float xrv[7], attv[7];
    #pragma unroll
    for (int k = 0; k < 7; k++) {
        int c = lane + 32 * k;
        bool ok = (c < CC);
        xrv[k]  = ok ? g_xr[n * HC + base + c] : 0.f;
        attv[k] = ok ? att[base + c] : 0.f;
    }

    float acc[7];
    #pragma unroll
    for (int k = 0; k < 7; k++) acc[k] = 0.f;
    float m = -CUDART_INF_F;
    float denom = 0.f;

    const int e0 = g_rowptr[n];
    const int e1 = g_rowptr[n + 1];

    for (int e = e0 + warp; e < e1; e += 4) {
        int s = g_col[e];
        const float* xls = g_xl + s * HC + base;
        float xlv[7];
        float dot = 0.f;
        #pragma unroll
        for (int k = 0; k < 7; k++) {
            int c = lane + 32 * k;
            float v = (c < CC) ? __ldg(xls + c) : 0.f;
            xlv[k] = v;
            float t = v + xrv[k];
            t = (t > 0.f) ? t : 0.2f * t;
            dot = fmaf(t, attv[k], dot);
        }
        #pragma unroll
        for (int off = 16; off > 0; off >>= 1)
            dot += __shfl_xor_sync(0xffffffffu, dot, off);

        float w;
        if (dot > m) {
            float scale = (m == -CUDART_INF_F) ? 0.f : __expf(m - dot);
            #pragma unroll
            for (int k = 0; k < 7; k++) acc[k] *= scale;
            denom *= scale;
            m = dot;
            w = 1.f;
        } else {
            w = __expf(dot - m);
        }
        denom += w;
        #pragma unroll
        for (int k = 0; k < 7; k++) acc[k] = fmaf(w, xlv[k], acc[k]);
    }

    if (lane == 0) sm_m[warp] = m;
    __syncthreads();

    float M = fmaxf(fmaxf(sm_m[0], sm_m[1]), fmaxf(sm_m[2], sm_m[3]));
    float f = __expf(m - M);
    #pragma unroll
    for (int k = 0; k < 7; k++) {
        int c = lane + 32 * k;
        if (c < CC) sm_acc[warp][c] = acc[k] * f;
    }
    if (lane == 0) sm_d[warp] = denom * f;
    __syncthreads();

    float D = sm_d[0] + sm_d[1] + sm_d[2] + sm_d[3];
    float invD = 1.f / D;
    for (int c = threadIdx.x; c < CC; c += 128) {
        float v = (sm_acc[0][c] + sm_acc[1][c] + sm_acc[2][c] + sm_acc[3][c]) * invD
                  + bias[base + c];
        if (do_relu) v = fmaxf(v, 0.f);
        g_h[n * HC + base + c] = v;
    }
}

// ---------------- Layer-2 attention fused with FC head -------------------------
__global__ void __launch_bounds__(128)
attn_fc_kernel(const float* __restrict__ att,
               const float* __restrict__ bias,
               const float* __restrict__ fcW,
               const float* __restrict__ fcb,
               float* __restrict__ out) {
    const int n    = blockIdx.x >> 1;
    const int hh   = blockIdx.x & 1;
    const int warp = threadIdx.x >> 5;
    const int lane = threadIdx.x & 31;
    const int tid  = threadIdx.x;
    const int base = hh * CC;

    __shared__ float sm_m[4];
    __shared__ float sm_d[4];
    __shared__ float sm_acc[4][CC];
    __shared__ float sm_h[CC];
    __shared__ int s_old;

    float xrv[7], attv[7];
    #pragma unroll
    for (int k = 0; k < 7; k++) {
        int c = lane + 32 * k;
        bool ok = (c < CC);
        xrv[k]  = ok ? g_xr[n * HC + base + c] : 0.f;
        attv[k] = ok ? att[base + c] : 0.f;
    }

    float acc[7];
    #pragma unroll
    for (int k = 0; k < 7; k++) acc[k] = 0.f;
    float m = -CUDART_INF_F;
    float denom = 0.f;

    const int e0 = g_rowptr[n];
    const int e1 = g_rowptr[n + 1];

    for (int e = e0 + warp; e < e1; e += 4) {
        int s = g_col[e];
        const float* xls = g_xl + s * HC + base;
        float xlv[7];
        float dot = 0.f;
        #pragma unroll
        for (int k = 0; k < 7; k++) {
            int c = lane + 32 * k;
            float v = (c < CC) ? __ldg(xls + c) : 0.f;
            xlv[k] = v;
            float t = v + xrv[k];
            t = (t > 0.f) ? t : 0.2f * t;
            dot = fmaf(t, attv[k], dot);
        }
        #pragma unroll
        for (int off = 16; off > 0; off >>= 1)
            dot += __shfl_xor_sync(0xffffffffu, dot, off);

        float w;
        if (dot > m) {
            float scale = (m == -CUDART_INF_F) ? 0.f : __expf(m - dot);
            #pragma unroll
            for (int k = 0; k < 7; k++) acc[k] *= scale;
            denom *= scale;
            m = dot;
            w = 1.f;
        } else {
            w = __expf(dot - m);
        }
        denom += w;
        #pragma unroll
        for (int k = 0; k < 7; k++) acc[k] = fmaf(w, xlv[k], acc[k]);
    }

    if (lane == 0) sm_m[warp] = m;
    __syncthreads();

    float M = fmaxf(fmaxf(sm_m[0], sm_m[1]), fmaxf(sm_m[2], sm_m[3]));
    float f = __expf(m - M);
    #pragma unroll
    for (int k = 0; k < 7; k++) {
        int c = lane + 32 * k;
        if (c < CC) sm_acc[warp][c] = acc[k] * f;
    }
    if (lane == 0) sm_d[warp] = denom * f;
    __syncthreads();

    float D = sm_d[0] + sm_d[1] + sm_d[2] + sm_d[3];
    float invD = 1.f / D;
    for (int c = tid; c < CC; c += 128) {
        sm_h[c] = (sm_acc[0][c] + sm_acc[1][c] + sm_acc[2][c] + sm_acc[3][c]) * invD
                  + bias[base + c];
    }
    __syncthreads();

    // ---- FC part: rows (n*HC + base + r), r in [0,200) ----
    if (tid < 125) {
        const float4* Wr4 = reinterpret_cast<const float4*>(fcW + (size_t)(n * HC + base) * FCO);
        float4 acc0 = make_float4(0.f, 0.f, 0.f, 0.f);
        float4 acc1 = make_float4(0.f, 0.f, 0.f, 0.f);
        #pragma unroll 2
        for (int r = 0; r < CC; r += 2) {
            float f0 = sm_h[r];
            float f1 = sm_h[r + 1];
            const float4* p0 = Wr4 + (size_t)r * 250 + 2 * tid;
            const float4* p1 = p0 + 250;
            float4 a0 = __ldg(p0);
            float4 a1 = __ldg(p0 + 1);
            float4 b0 = __ldg(p1);
            float4 b1 = __ldg(p1 + 1);
            acc0.x = fmaf(f0, a0.x, fmaf(f1, b0.x, acc0.x));
            acc0.y = fmaf(f0, a0.y, fmaf(f1, b0.y, acc0.y));
            acc0.z = fmaf(f0, a0.z, fmaf(f1, b0.z, acc0.z));
            acc0.w = fmaf(f0, a0.w, fmaf(f1, b0.w, acc0.w));
            acc1.x = fmaf(f0, a1.x, fmaf(f1, b1.x, acc1.x));
            acc1.y = fmaf(f0, a1.y, fmaf(f1, b1.y, acc1.y));
            acc1.z = fmaf(f0, a1.z, fmaf(f1, b1.z, acc1.z));
            acc1.w = fmaf(f0, a1.w, fmaf(f1, b1.w, acc1.w));
        }
        int j = 8 * tid;
        atomicAdd(&g_fc[j + 0], acc0.x);
        atomicAdd(&g_fc[j + 1], acc0.y);
        atomicAdd(&g_fc[j + 2], acc0.z);
        atomicAdd(&g_fc[j + 3], acc0.w);
        atomicAdd(&g_fc[j + 4], acc1.x);
        atomicAdd(&g_fc[j + 5], acc1.y);
        atomicAdd(&g_fc[j + 6], acc1.z);
        atomicAdd(&g_fc[j + 7], acc1.w);
    }

    __threadfence();
    __syncthreads();
    if (tid == 0) s_old = atomicAdd(&g_ticket, 1);
    __syncthreads();
    if (s_old == (int)gridDim.x - 1) {
        __threadfence();
        for (int j = tid; j < FCO; j += 128) {
            float v = __ldcg(&g_fc[j]) + fcb[j];
            out[j] = fmaxf(v, 0.f);
        }
    }
}

// ---------------- launch -------------------------------------------------------
extern "C" void kernel_launch(void* const* d_in, const int* in_sizes, int n_in,
                              void* d_out, int out_size) {
    const float* x   = (const float*)d_in[0];
    const int*   ei  = (const int*)  d_in[1];
    const float* Wl0 = (const float*)d_in[2];
    const float* bl0 = (const float*)d_in[3];
    const float* Wr0 = (const float*)d_in[4];
    const float* br0 = (const float*)d_in[5];
    const float* at0 = (const float*)d_in[6];
    const float* b0  = (const float*)d_in[7];
    const float* Wl1 = (const float*)d_in[8];
    const float* bl1 = (const float*)d_in[9];
    const float* Wr1 = (const float*)d_in[10];
    const float* br1 = (const float*)d_in[11];
    const float* at1 = (const float*)d_in[12];
    const float* b1  = (const float*)d_in[13];
    const float* Wl2 = (const float*)d_in[14];
    const float* bl2 = (const float*)d_in[15];
    const float* Wr2 = (const float*)d_in[16];
    const float* br2 = (const float*)d_in[17];
    const float* at2 = (const float*)d_in[18];
    const float* b2  = (const float*)d_in[19];
    const float* fcW = (const float*)d_in[20];
    const float* fcb = (const float*)d_in[21];
    float* out = (float*)d_out;

    int E = in_sizes[1] / 2;

    csr_build_kernel<<<1, NN>>>(ei, E);

    dim3 ggrid((HC + 63) / 64, NN / 16, 2);
    dim3 agrid(NN * HH);

    gemm_kernel<<<ggrid, 128>>>(x, 1, Wl0, bl0, Wr0, br0, DIN);
    attn_kernel<<<agrid, 128>>>(at0, b0, 1);
    gemm_kernel<<<ggrid, 128>>>(x, 0, Wl1, bl1, Wr1, br1, HC);
    attn_kernel<<<agrid, 128>>>(at1, b1, 1);
    gemm_kernel<<<ggrid, 128>>>(x, 0, Wl2, bl2, Wr2, br2, HC);
    attn_fc_kernel<<<agrid, 128>>>(at2, b2, fcW, fcb, out);
}

// round 15
// speedup vs baseline: 1.1439x; 1.1439x over previous
#include <cuda_runtime.h>
#include <math_constants.h>

#define NN   512
#define DIN  128
#define HH   2
#define CC   200
#define HC   400
#define FCO  1000
#define ETOT_MAX (32768 + NN)

// ---------------- device-global scratch ---------------------------------------
__device__ float g_xl[NN * HC];
__device__ float g_xr[NN * HC];
__device__ float g_h [NN * HC];
__device__ int   g_rowptr[NN + 1];
__device__ int   g_col[ETOT_MAX];
__device__ float g_fc[FCO];
__device__ int   g_ticket;

// ---------------- CSR build: single block, 512 threads ------------------------
__global__ void csr_build_kernel(const int* __restrict__ ei, int E) {
    __shared__ int s[NN];
    __shared__ int cur[NN];
    int t = threadIdx.x;

    if (t < 500) { g_fc[t] = 0.f; g_fc[t + 500] = 0.f; }
    if (t == 0) g_ticket = 0;
    s[t] = 0;
    __syncthreads();

    int Etot = E + NN;
    for (int e = t; e < Etot; e += NN) {
        int dst = (e < E) ? ei[E + e] : (e - E);
        atomicAdd(&s[dst], 1);
    }
    __syncthreads();

    int cnt = s[t];
    #pragma unroll
    for (int off = 1; off < NN; off <<= 1) {
        int v = (t >= off) ? s[t - off] : 0;
        __syncthreads();
        s[t] += v;
        __syncthreads();
    }
    g_rowptr[t + 1] = s[t];
    if (t == 0) g_rowptr[0] = 0;
    cur[t] = s[t] - cnt;
    __syncthreads();

    for (int e = t; e < Etot; e += NN) {
        int src, dst;
        if (e < E) { src = ei[e]; dst = ei[E + e]; }
        else       { src = dst = e - E; }
        int p = atomicAdd(&cur[dst], 1);
        g_col[p] = src;
    }
}

// ---------------- GEMM: 16x64 tile, BK=16, 128 threads, double-buffered smem ---
__global__ void __launch_bounds__(128)
gemm_kernel(const float* __restrict__ Aext, int useAext,
            const float* __restrict__ Wl, const float* __restrict__ bl,
            const float* __restrict__ Wr, const float* __restrict__ br,
            int K) {
    const float* A    = useAext ? Aext : g_h;
    const float* B    = blockIdx.z ? Wr : Wl;
    const float* bias = blockIdx.z ? br : bl;
    float*       Cout = blockIdx.z ? g_xr : g_xl;

    __shared__ float As[2][16][17];
    __shared__ float Bs[2][16][64];

    const int tid = threadIdx.x;
    const int tx = tid & 15;
    const int ty = tid >> 4;
    const int rowBase = blockIdx.y * 16;
    const int colBase = blockIdx.x * 64;

    const int a_m  = tid >> 3;
    const int a_k2 = (tid & 7) * 2;
    const int b_k  = tid >> 3;
    const int b_n8 = (tid & 7) * 8;

    const int nTiles = K >> 4;

    float2 pa;
    float4 pb0, pb1;

    {
        pa = *reinterpret_cast<const float2*>(&A[(rowBase + a_m) * K + a_k2]);
        int ncol = colBase + b_n8;
        if (ncol + 7 < HC) {
            pb0 = *reinterpret_cast<const float4*>(&B[b_k * HC + ncol]);
            pb1 = *reinterpret_cast<const float4*>(&B[b_k * HC + ncol + 4]);
        } else {
            float tmp[8];
            #pragma unroll
            for (int j = 0; j < 8; j++)
                tmp[j] = (ncol + j < HC) ? B[b_k * HC + ncol + j] : 0.f;
            pb0 = make_float4(tmp[0], tmp[1], tmp[2], tmp[3]);
            pb1 = make_float4(tmp[4], tmp[5], tmp[6], tmp[7]);
        }
        As[0][a_k2 + 0][a_m] = pa.x;
        As[0][a_k2 + 1][a_m] = pa.y;
        *reinterpret_cast<float4*>(&Bs[0][b_k][b_n8])     = pb0;
        *reinterpret_cast<float4*>(&Bs[0][b_k][b_n8 + 4]) = pb1;
    }
    __syncthreads();

    float acc[2][4];
    #pragma unroll
    for (int i = 0; i < 2; i++)
        #pragma unroll
        for (int j = 0; j < 4; j++) acc[i][j] = 0.f;

    for (int t = 0; t < nTiles; t++) {
        const int cur = t & 1;
        const bool more = (t + 1 < nTiles);

        if (more) {
            int k0 = (t + 1) << 4;
            pa = *reinterpret_cast<const float2*>(&A[(rowBase + a_m) * K + k0 + a_k2]);
            int ncol = colBase + b_n8;
            if (ncol + 7 < HC) {
                pb0 = *reinterpret_cast<const float4*>(&B[(k0 + b_k) * HC + ncol]);
                pb1 = *reinterpret_cast<const float4*>(&B[(k0 + b_k) * HC + ncol + 4]);
            } else {
                float tmp[8];
                #pragma unroll
                for (int j = 0; j < 8; j++)
                    tmp[j] = (ncol + j < HC) ? B[(k0 + b_k) * HC + ncol + j] : 0.f;
                pb0 = make_float4(tmp[0], tmp[1], tmp[2], tmp[3]);
                pb1 = make_float4(tmp[4], tmp[5], tmp[6], tmp[7]);
            }
        }

        #pragma unroll
        for (int k = 0; k < 16; k++) {
            float a0 = As[cur][k][2 * ty];
            float a1 = As[cur][k][2 * ty + 1];
            float4 b = *reinterpret_cast<const float4*>(&Bs[cur][k][4 * tx]);
            acc[0][0] = fmaf(a0, b.x, acc[0][0]);
            acc[0][1] = fmaf(a0, b.y, acc[0][1]);
            acc[0][2] = fmaf(a0, b.z, acc[0][2]);
            acc[0][3] = fmaf(a0, b.w, acc[0][3]);
            acc[1][0] = fmaf(a1, b.x, acc[1][0]);
            acc[1][1] = fmaf(a1, b.y, acc[1][1]);
            acc[1][2] = fmaf(a1, b.z, acc[1][2]);
            acc[1][3] = fmaf(a1, b.w, acc[1][3]);
        }

        if (more) {
            const int nxt = cur ^ 1;
            As[nxt][a_k2 + 0][a_m] = pa.x;
            As[nxt][a_k2 + 1][a_m] = pa.y;
            *reinterpret_cast<float4*>(&Bs[nxt][b_k][b_n8])     = pb0;
            *reinterpret_cast<float4*>(&Bs[nxt][b_k][b_n8 + 4]) = pb1;
            __syncthreads();
        }
    }

    const int r0 = rowBase + 2 * ty;
    const int c0 = colBase + 4 * tx;
    #pragma unroll
    for (int j = 0; j < 4; j++) {
        int c = c0 + j;
        if (c < HC) {
            float bb = bias[c];
            Cout[r0 * HC + c]       = acc[0][j] + bb;
            Cout[(r0 + 1) * HC + c] = acc[1][j] + bb;
        }
    }
}

// ---------------- GATv2 attention (layers 0,1): 128 threads/block --------------
__global__ void attn_kernel(const float* __restrict__ att,
                            const float* __restrict__ bias,
                            int do_relu) {
    const int n    = blockIdx.x >> 1;
    const int hh   = blockIdx.x & 1;
    const int warp = threadIdx.x >> 5;
    const int lane = threadIdx.x & 31;
    const int base = hh * CC;

    __shared__ float sm_m[4];
    __shared__ float sm_d[4];
    __shared__ float sm_acc[4][CC];

    float xrv[7], attv[7];
    #pragma unroll
    for (int k = 0; k < 7; k++) {
        int c = lane + 32 * k;
        bool ok = (c < CC);
        xrv[k]  = ok ? g_xr[n * HC + base + c] : 0.f;
        attv[k] = ok ? att[base + c] : 0.f;
    }

    float acc[7];
    #pragma unroll
    for (int k = 0; k < 7; k++) acc[k] = 0.f;
    float m = -CUDART_INF_F;
    float denom = 0.f;

    const int e0 = g_rowptr[n];
    const int e1 = g_rowptr[n + 1];

    for (int e = e0 + warp; e < e1; e += 4) {
        int s = g_col[e];
        const float* xls = g_xl + s * HC + base;
        float xlv[7];
        float dot = 0.f;
        #pragma unroll
        for (int k = 0; k < 7; k++) {
            int c = lane + 32 * k;
            float v = (c < CC) ? __ldg(xls + c) : 0.f;
            xlv[k] = v;
            float t = v + xrv[k];
            t = (t > 0.f) ? t : 0.2f * t;
            dot = fmaf(t, attv[k], dot);
        }
        #pragma unroll
        for (int off = 16; off > 0; off >>= 1)
            dot += __shfl_xor_sync(0xffffffffu, dot, off);

        float w;
        if (dot > m) {
            float scale = (m == -CUDART_INF_F) ? 0.f : __expf(m - dot);
            #pragma unroll
            for (int k = 0; k < 7; k++) acc[k] *= scale;
            denom *= scale;
            m = dot;
            w = 1.f;
        } else {
            w = __expf(dot - m);
        }
        denom += w;
        #pragma unroll
        for (int k = 0; k < 7; k++) acc[k] = fmaf(w, xlv[k], acc[k]);
    }

    if (lane == 0) sm_m[warp] = m;
    __syncthreads();

    float M = fmaxf(fmaxf(sm_m[0], sm_m[1]), fmaxf(sm_m[2], sm_m[3]));
    float f = __expf(m - M);
    #pragma unroll
    for (int k = 0; k < 7; k++) {
        int c = lane + 32 * k;
        if (c < CC) sm_acc[warp][c] = acc[k] * f;
    }
    if (lane == 0) sm_d[warp] = denom * f;
    __syncthreads();

    float D = sm_d[0] + sm_d[1] + sm_d[2] + sm_d[3];
    float invD = 1.f / D;
    for (int c = threadIdx.x; c < CC; c += 128) {
        float v = (sm_acc[0][c] + sm_acc[1][c] + sm_acc[2][c] + sm_acc[3][c]) * invD
                  + bias[base + c];
        if (do_relu) v = fmaxf(v, 0.f);
        g_h[n * HC + base + c] = v;
    }
}

// ---------------- Layer-2 attention fused with FC head (256 threads, R10) ------
__global__ void __launch_bounds__(256)
attn_fc_kernel(const float* __restrict__ att,
               const float* __restrict__ bias,
               const float* __restrict__ fcW,
               const float* __restrict__ fcb,
               float* __restrict__ out) {
    const int n    = blockIdx.x >> 1;
    const int hh   = blockIdx.x & 1;
    const int warp = threadIdx.x >> 5;   // 0..7
    const int lane = threadIdx.x & 31;
    const int tid  = threadIdx.x;
    const int base = hh * CC;

    __shared__ float sm_m[8];
    __shared__ float sm_d[8];
    __shared__ float sm_acc[8][CC];
    __shared__ float sm_h[CC];
    __shared__ int s_old;

    float xrv[7], attv[7];
    #pragma unroll
    for (int k = 0; k < 7; k++) {
        int c = lane + 32 * k;
        bool ok = (c < CC);
        xrv[k]  = ok ? g_xr[n * HC + base + c] : 0.f;
        attv[k] = ok ? att[base + c] : 0.f;
    }

    float acc[7];
    #pragma unroll
    for (int k = 0; k < 7; k++) acc[k] = 0.f;
    float m = -CUDART_INF_F;
    float denom = 0.f;

    const int e0 = g_rowptr[n];
    const int e1 = g_rowptr[n + 1];

    for (int e = e0 + warp; e < e1; e += 8) {
        int s = g_col[e];
        const float* xls = g_xl + s * HC + base;
        float xlv[7];
        float dot = 0.f;
        #pragma unroll
        for (int k = 0; k < 7; k++) {
            int c = lane + 32 * k;
            float v = (c < CC) ? __ldg(xls + c) : 0.f;
            xlv[k] = v;
            float t = v + xrv[k];
            t = (t > 0.f) ? t : 0.2f * t;
            dot = fmaf(t, attv[k], dot);
        }
        #pragma unroll
        for (int off = 16; off > 0; off >>= 1)
            dot += __shfl_xor_sync(0xffffffffu, dot, off);

        float w;
        if (dot > m) {
            float scale = (m == -CUDART_INF_F) ? 0.f : __expf(m - dot);
            #pragma unroll
            for (int k = 0; k < 7; k++) acc[k] *= scale;
            denom *= scale;
            m = dot;
            w = 1.f;
        } else {
            w = __expf(dot - m);
        }
        denom += w;
        #pragma unroll
        for (int k = 0; k < 7; k++) acc[k] = fmaf(w, xlv[k], acc[k]);
    }

    if (lane == 0) sm_m[warp] = m;
    __syncthreads();

    float M = sm_m[0];
    #pragma unroll
    for (int w = 1; w < 8; w++) M = fmaxf(M, sm_m[w]);
    float f = __expf(m - M);                 // 0 for warps that saw no edges
    #pragma unroll
    for (int k = 0; k < 7; k++) {
        int c = lane + 32 * k;
        if (c < CC) sm_acc[warp][c] = acc[k] * f;
    }
    if (lane == 0) sm_d[warp] = denom * f;
    __syncthreads();

    float D = 0.f;
    #pragma unroll
    for (int w = 0; w < 8; w++) D += sm_d[w];
    float invD = 1.f / D;
    for (int c = tid; c < CC; c += 256) {
        float v = 0.f;
        #pragma unroll
        for (int w = 0; w < 8; w++) v += sm_acc[w][c];
        sm_h[c] = v * invD + bias[base + c];
    }
    __syncthreads();

    // ---- FC: rows (n*HC + base + r), r in [0,200); one float4 column per lane.
    // 4 rows per iteration -> 4 independent LDG.128 in flight.
    if (tid < 250) {
        const float4* Wr4 = reinterpret_cast<const float4*>(fcW + (size_t)(n * HC + base) * FCO);
        float4 facc = make_float4(0.f, 0.f, 0.f, 0.f);
        #pragma unroll 2
        for (int r = 0; r < CC; r += 4) {
            const float4* p = Wr4 + (size_t)r * 250 + tid;
            float4 w0 = __ldg(p);
            float4 w1 = __ldg(p + 250);
            float4 w2 = __ldg(p + 500);
            float4 w3 = __ldg(p + 750);
            float f0 = sm_h[r + 0];
            float f1 = sm_h[r + 1];
            float f2 = sm_h[r + 2];
            float f3 = sm_h[r + 3];
            facc.x = fmaf(f0, w0.x, fmaf(f1, w1.x, fmaf(f2, w2.x, fmaf(f3, w3.x, facc.x))));
            facc.y = fmaf(f0, w0.y, fmaf(f1, w1.y, fmaf(f2, w2.y, fmaf(f3, w3.y, facc.y))));
            facc.z = fmaf(f0, w0.z, fmaf(f1, w1.z, fmaf(f2, w2.z, fmaf(f3, w3.z, facc.z))));
            facc.w = fmaf(f0, w0.w, fmaf(f1, w1.w, fmaf(f2, w2.w, fmaf(f3, w3.w, facc.w))));
        }
        int j = 4 * tid;
        atomicAdd(&g_fc[j + 0], facc.x);
        atomicAdd(&g_fc[j + 1], facc.y);
        atomicAdd(&g_fc[j + 2], facc.z);
        atomicAdd(&g_fc[j + 3], facc.w);
    }

    __threadfence();
    __syncthreads();
    if (tid == 0) s_old = atomicAdd(&g_ticket, 1);
    __syncthreads();
    if (s_old == (int)gridDim.x - 1) {
        __threadfence();
        for (int j = tid; j < FCO; j += 256) {
            float v = __ldcg(&g_fc[j]) + fcb[j];
            out[j] = fmaxf(v, 0.f);
        }
    }
}

// ---------------- launch -------------------------------------------------------
extern "C" void kernel_launch(void* const* d_in, const int* in_sizes, int n_in,
                              void* d_out, int out_size) {
    const float* x   = (const float*)d_in[0];
    const int*   ei  = (const int*)  d_in[1];
    const float* Wl0 = (const float*)d_in[2];
    const float* bl0 = (const float*)d_in[3];
    const float* Wr0 = (const float*)d_in[4];
    const float* br0 = (const float*)d_in[5];
    const float* at0 = (const float*)d_in[6];
    const float* b0  = (const float*)d_in[7];
    const float* Wl1 = (const float*)d_in[8];
    const float* bl1 = (const float*)d_in[9];
    const float* Wr1 = (const float*)d_in[10];
    const float* br1 = (const float*)d_in[11];
    const float* at1 = (const float*)d_in[12];
    const float* b1  = (const float*)d_in[13];
    const float* Wl2 = (const float*)d_in[14];
    const float* bl2 = (const float*)d_in[15];
    const float* Wr2 = (const float*)d_in[16];
    const float* br2 = (const float*)d_in[17];
    const float* at2 = (const float*)d_in[18];
    const float* b2  = (const float*)d_in[19];
    const float* fcW = (const float*)d_in[20];
    const float* fcb = (const float*)d_in[21];
    float* out = (float*)d_out;

    int E = in_sizes[1] / 2;

    csr_build_kernel<<<1, NN>>>(ei, E);

    dim3 ggrid((HC + 63) / 64, NN / 16, 2);
    dim3 agrid(NN * HH);

    gemm_kernel<<<ggrid, 128>>>(x, 1, Wl0, bl0, Wr0, br0, DIN);
    attn_kernel<<<agrid, 128>>>(at0, b0, 1);
    gemm_kernel<<<ggrid, 128>>>(x, 0, Wl1, bl1, Wr1, br1, HC);
    attn_kernel<<<agrid, 128>>>(at1, b1, 1);
    gemm_kernel<<<ggrid, 128>>>(x, 0, Wl2, bl2, Wr2, br2, HC);
    attn_fc_kernel<<<agrid, 256>>>(at2, b2, fcW, fcb, out);
}